// round 6
// baseline (speedup 1.0000x reference)
#include <cuda_runtime.h>
#include <cstdint>

// AddRadiusEdgeIndex: pairwise squared distances + radius mask, N=8192, r=1.
// Output: [N*N] masked_dist2 (f32), then [N*N] edge_mask as 0.0/1.0 (f32).
//
// Numerics deliberately replicate the reference bit-exactly:
//   sq[i]  = x*x + y*y + z*z                (plain mul/add, no FMA contraction)
//   dot    = fma(z, z', fma(y, y', x*x))    (FMA chain, gemm-like)
//   d2     = (sq_i + sq_j) - 2*dot ;  d2 = max(d2, 0) ; mask = d2 <= 1
//
// HBM-store-bound: 512 MB written. Tile 16 rows x 512 cols so every row the
// block writes is a single 2 KB contiguous span (matches the 2 KB addr->die
// interleave grain). Evict-streaming 256-bit stores.

#define TI 16
#define TJ 512
#define R2 1.0f

__device__ __forceinline__ void stg256_cs(float* p,
                                          float v0, float v1, float v2, float v3,
                                          float v4, float v5, float v6, float v7)
{
    asm volatile("st.global.cs.v8.f32 [%0], {%1,%2,%3,%4,%5,%6,%7,%8};"
                 :: "l"(p), "f"(v0), "f"(v1), "f"(v2), "f"(v3),
                    "f"(v4), "f"(v5), "f"(v6), "f"(v7)
                 : "memory");
}

__global__ __launch_bounds__(256, 3)
void radius_edge_kernel(const float* __restrict__ pos,
                        float* __restrict__ dist_out,
                        float* __restrict__ mask_out,
                        int n)
{
    __shared__ float jx[TJ], jy[TJ], jz[TJ], jsq[TJ];
    __shared__ float ix[TI], iy[TI], iz[TI], isq[TI];

    const int j0 = blockIdx.x * TJ;
    const int i0 = blockIdx.y * TI;
    const int t  = threadIdx.x;   // 256 threads

    // Stage tiles. sq uses plain mul/add rounding (matches jnp.sum(pos*pos)).
#pragma unroll
    for (int s = 0; s < TJ / 256; ++s) {
        int lj = t + s * 256;
        int j  = j0 + lj;
        float x = pos[3 * j + 0];
        float y = pos[3 * j + 1];
        float z = pos[3 * j + 2];
        jx[lj] = x; jy[lj] = y; jz[lj] = z;
        jsq[lj] = __fadd_rn(__fadd_rn(__fmul_rn(x, x), __fmul_rn(y, y)),
                            __fmul_rn(z, z));
    }
    if (t < TI) {
        int i = i0 + t;
        float x = pos[3 * i + 0];
        float y = pos[3 * i + 1];
        float z = pos[3 * i + 2];
        ix[t] = x; iy[t] = y; iz[t] = z;
        isq[t] = __fadd_rn(__fadd_rn(__fmul_rn(x, x), __fmul_rn(y, y)),
                           __fmul_rn(z, z));
    }
    __syncthreads();

    // Thread layout: tx in [0,64) -> 8 consecutive j, ty in [0,4) -> i stride.
    const int tx = t & 63;
    const int ty = t >> 6;
    const int jj = tx * 8;

    // Pull the j-octet into registers once.
    float xj[8], yj[8], zj[8], sj[8];
#pragma unroll
    for (int q = 0; q < 8; ++q) {
        xj[q] = jx[jj + q];
        yj[q] = jy[jj + q];
        zj[q] = jz[jj + q];
        sj[q] = jsq[jj + q];
    }

    // Row pointers: start at row (i0+ty), advance 4 rows per iteration.
    const size_t base = (size_t)(i0 + ty) * (size_t)n + (size_t)(j0 + jj);
    float* __restrict__ dptr = dist_out + base;
    float* __restrict__ mptr = mask_out ? mask_out + base : nullptr;
    const size_t rowstep = (size_t)n * 4;     // 4 rows, in floats

#pragma unroll
    for (int k = 0; k < TI / 4; ++k) {
        const int il = ty + k * 4;            // local i (0..15)
        const float xi = ix[il], yi = iy[il], zi = iz[il], si = isq[il];

        float d[8], m[8];
#pragma unroll
        for (int q = 0; q < 8; ++q) {
            float dt = __fmaf_rn(zi, zj[q], __fmaf_rn(yi, yj[q], __fmul_rn(xi, xj[q])));
            float dd = __fsub_rn(__fadd_rn(si, sj[q]), __fadd_rn(dt, dt));
            dd = fmaxf(dd, 0.0f);
            m[q] = (dd <= R2) ? 1.0f : 0.0f;
            d[q] = (m[q] != 0.0f) ? dd : 0.0f;
        }

        stg256_cs(dptr, d[0], d[1], d[2], d[3], d[4], d[5], d[6], d[7]);
        dptr += rowstep;
        if (mptr) {
            stg256_cs(mptr, m[0], m[1], m[2], m[3], m[4], m[5], m[6], m[7]);
            mptr += rowstep;
        }
    }
}

extern "C" void kernel_launch(void* const* d_in, const int* in_sizes, int n_in,
                              void* d_out, int out_size)
{
    const float* pos = (const float*)d_in[0];
    const int n = in_sizes[0] / 3;           // 8192

    float* out  = (float*)d_out;
    float* dist = out;
    const long long nn = (long long)n * (long long)n;
    float* mask = ((long long)out_size >= 2 * nn) ? (out + (size_t)nn) : nullptr;

    dim3 grid((n + TJ - 1) / TJ, (n + TI - 1) / TI);
    radius_edge_kernel<<<grid, 256>>>(pos, dist, mask, n);
}